// round 4
// baseline (speedup 1.0000x reference)
#include <cuda_runtime.h>
#include <cstdint>

// N=8192 tokens, D=128, x layout [8,384,32,32] fp32 (feature-major)
#define NTILES 64
#define SCALE 0.08838834764831845f  // 1/sqrt(128)

// smem layout (floats). Q/K/V XOR-swizzled (no padding), P padded stride 132.
#define Q_OFF   0          // 64 x 128
#define K_OFF   8192       // 128 x 128
#define V_OFF   24576      // 128 x 128
#define P_OFF   40960      // 2 buffers of 64 x 132
#define PST     132
#define P_SZ    (64 * PST) // 8448
#define RS4_OFF 57856      // 64 x 2 partial rowsums
#define RS_OFF  57984      // 64 inverse rowsums
#define SMEM_FLOATS 58048
#define SMEM_BYTES (SMEM_FLOATS * 4)   // 232192 <= 232448

extern __shared__ float sm[];

__device__ __forceinline__ uint32_t sptr(const void* p) {
    return (uint32_t)__cvta_generic_to_shared(p);
}
__device__ __forceinline__ void cp16(const float* smem_dst, const float* gsrc) {
    asm volatile("cp.async.cg.shared.global [%0], [%1], 16;"
                 :: "r"(sptr(smem_dst)), "l"(gsrc));
}
__device__ __forceinline__ void cp_commit() { asm volatile("cp.async.commit_group;"); }
__device__ __forceinline__ void cp_wait0()  { asm volatile("cp.async.wait_group 0;"); }

__device__ __forceinline__ void bar_sync(int id, int cnt) {
    asm volatile("bar.sync %0, %1;" :: "r"(id), "r"(cnt) : "memory");
}
__device__ __forceinline__ void bar_arrive(int id, int cnt) {
    asm volatile("bar.arrive %0, %1;" :: "r"(id), "r"(cnt) : "memory");
}

__device__ __forceinline__ float tf32r(float x) {
    uint32_t u; asm("cvt.rna.tf32.f32 %0, %1;" : "=r"(u) : "f"(x));
    return __uint_as_float(u);
}
__device__ __forceinline__ void mma8(float c[4], const uint32_t a[4], const uint32_t b[2]) {
    asm volatile("mma.sync.aligned.m16n8k8.row.col.f32.tf32.tf32.f32 "
                 "{%0,%1,%2,%3}, {%4,%5,%6,%7}, {%8,%9}, {%0,%1,%2,%3};"
                 : "+f"(c[0]), "+f"(c[1]), "+f"(c[2]), "+f"(c[3])
                 : "r"(a[0]), "r"(a[1]), "r"(a[2]), "r"(a[3]),
                   "r"(b[0]), "r"(b[1]));
}

// K tile: element (feature r, token c) at r*128 + ((c16 ^ swzK(r&7))<<2 | c&3)
// swzK(e) = ((e&3)<<1) | ((e>>2)&1)  -- makes B-fragment loads conflict-free.
__device__ __forceinline__ void issue_K(const float* g, int t) {
#pragma unroll
    for (int i = 0; i < 32; i++) {
        int u = i * 128 + t;           // 16B-unit id, 0..4095
        int r = u >> 5, c = u & 31;
        int sw = c ^ (((r & 3) << 1) | ((r >> 2) & 1));
        cp16(sm + K_OFF + r * 128 + (sw << 2), g + (size_t)r * 1024 + (c << 2));
    }
}
// V tile: unit swizzle u ^= (r&7) -- makes A-fragment loads conflict-free.
__device__ __forceinline__ void issue_V(const float* g, int t) {
#pragma unroll
    for (int i = 0; i < 32; i++) {
        int u = i * 128 + t;
        int r = u >> 5, c = u & 31;
        int sw = c ^ (r & 7);
        cp16(sm + V_OFF + r * 128 + (sw << 2), g + (size_t)r * 1024 + (c << 2));
    }
}

__global__ void __launch_bounds__(256, 1)
conv_attn_kernel(const float* __restrict__ x, float* __restrict__ out) {
    const int tid  = threadIdx.x;
    const int lane = tid & 31;
    const int wid  = tid >> 5;
    const int g    = lane >> 2;
    const int t4   = lane & 3;

    const int bq  = blockIdx.x >> 4;
    const int sq0 = (blockIdx.x & 15) << 6;
    const float* Qg = x + (size_t)bq * 393216u + 262144u + sq0;

    // ---- Q: all 256 threads load + transpose + tf32-round, XOR-swizzled ----
    // Q[m][j ^ ((m&7)<<2)]
#pragma unroll
    for (int i = 0; i < 32; i++) {
        int idx = i * 256 + tid;
        int m = idx & 63, j = idx >> 6;
        sm[Q_OFF + m * 128 + (j ^ ((m & 7) << 2))] = tf32r(Qg[(size_t)j * 1024 + m]);
    }

    // prefetch tile 0: S-group loads K, PV-group loads V
    if (tid < 128) { issue_K(x + 131072u, tid); }
    else           { issue_V(x,           tid - 128); }
    cp_commit();
    __syncthreads();   // Q visible to S-group

    if (wid < 4) {
        // ================= S GROUP (warps 0-3): S = Q K^T, softmax, P =================
        const int qrow = (wid >> 1) * 32;   // 2x2 warp grid of 32x64 tiles
        const int scol = (wid & 1) * 64;
        const int g4 = g << 2;
        float racc0[2] = {0.f, 0.f}, racc1[2] = {0.f, 0.f};

        for (int kt = 0; kt < NTILES; ++kt) {
            cp_wait0();
            bar_sync(1, 128);                 // K(kt) ready, visible to group

            float c[2][8][4];
#pragma unroll
            for (int mt = 0; mt < 2; mt++)
#pragma unroll
                for (int nt = 0; nt < 8; nt++)
#pragma unroll
                    for (int r = 0; r < 4; r++) c[mt][nt][r] = 0.f;

#pragma unroll 4
            for (int ks = 0; ks < 16; ks++) {
                const int j0 = ks * 8;
                uint32_t a[2][4], b[8][2];
#pragma unroll
                for (int mt = 0; mt < 2; mt++) {
                    const float* A = sm + Q_OFF + (qrow + mt * 16 + g) * 128;
                    const int i0 = (j0 + t4) ^ g4;
                    const int i1 = (j0 + t4 + 4) ^ g4;
                    a[mt][0] = __float_as_uint(A[i0]);
                    a[mt][1] = __float_as_uint(A[1024 + i0]);   // row+8
                    a[mt][2] = __float_as_uint(A[i1]);
                    a[mt][3] = __float_as_uint(A[1024 + i1]);
                }
#pragma unroll
                for (int nt = 0; nt < 8; nt++) {
                    const int col = scol + nt * 8 + g;
                    const int cu = col >> 2, cl = col & 3;
                    b[nt][0] = __float_as_uint(
                        sm[K_OFF + (j0 + t4) * 128 + ((cu ^ (2 * t4)) << 2) + cl]);
                    b[nt][1] = __float_as_uint(
                        sm[K_OFF + (j0 + t4 + 4) * 128 + ((cu ^ (2 * t4 + 1)) << 2) + cl]);
                }
#pragma unroll
                for (int mt = 0; mt < 2; mt++)
#pragma unroll
                    for (int nt = 0; nt < 8; nt++)
                        mma8(c[mt][nt], a[mt], b[nt]);
            }

            bar_sync(1, 128);                 // all S warps done reading K
            if (kt + 1 < NTILES) {
                const int n = kt + 1;
                issue_K(x + (size_t)(n >> 3) * 393216u + 131072u + ((n & 7) << 7), tid);
            }
            cp_commit();

            if (kt >= 2) bar_sync(5 + (kt & 1), 256);   // P buffer free

            float* P = sm + P_OFF + (kt & 1) * P_SZ;
#pragma unroll
            for (int mt = 0; mt < 2; mt++) {
                float s0 = 0.f, s1 = 0.f;
                const int row = qrow + mt * 16 + g;
#pragma unroll
                for (int nt = 0; nt < 8; nt++) {
                    float p0 = tf32r(__expf(c[mt][nt][0] * SCALE));
                    float p1 = tf32r(__expf(c[mt][nt][1] * SCALE));
                    float p2 = tf32r(__expf(c[mt][nt][2] * SCALE));
                    float p3 = tf32r(__expf(c[mt][nt][3] * SCALE));
                    s0 += p0 + p1; s1 += p2 + p3;
                    const int col = scol + nt * 8 + 2 * t4;
                    *(float2*)(P + row * PST + col)       = make_float2(p0, p1);
                    *(float2*)(P + (row + 8) * PST + col) = make_float2(p2, p3);
                }
                s0 += __shfl_xor_sync(0xffffffffu, s0, 1);
                s0 += __shfl_xor_sync(0xffffffffu, s0, 2);
                s1 += __shfl_xor_sync(0xffffffffu, s1, 1);
                s1 += __shfl_xor_sync(0xffffffffu, s1, 2);
                racc0[mt] += s0; racc1[mt] += s1;
            }
            bar_arrive(3 + (kt & 1), 256);    // P(kt) full
        }

        // partial rowsums -> smem (2 column-halves per row)
        if (t4 == 0) {
#pragma unroll
            for (int mt = 0; mt < 2; mt++) {
                const int row = qrow + mt * 16 + g;
                sm[RS4_OFF + row * 2 + (wid & 1)]       = racc0[mt];
                sm[RS4_OFF + (row + 8) * 2 + (wid & 1)] = racc1[mt];
            }
        }
        bar_arrive(3, 256);                   // signal rowsums ready (id 3 is free now)
    } else {
        // ================= PV GROUP (warps 4-7): O^T += V^T P^T =================
        const int widp = wid - 4;
        const int vrow = (widp >> 1) * 64;    // 2x2 warp grid of 64x32 tiles
        const int mcol = (widp & 1) * 32;
        const int t128 = tid - 128;

        float o[4][4][4];
#pragma unroll
        for (int a = 0; a < 4; a++)
#pragma unroll
            for (int b = 0; b < 4; b++)
#pragma unroll
                for (int r = 0; r < 4; r++) o[a][b][r] = 0.f;

        for (int kt = 0; kt < NTILES; ++kt) {
            bar_sync(3 + (kt & 1), 256);      // P(kt) ready
            cp_wait0();
            bar_sync(2, 128);                 // V(kt) ready, visible to group

            const float* P = sm + P_OFF + (kt & 1) * P_SZ;
#pragma unroll 4
            for (int ks = 0; ks < 16; ks++) {
                const int k0 = ks * 8;
                uint32_t a[4][4], b[4][2];
#pragma unroll
                for (int vt = 0; vt < 4; vt++) {
                    const float* A = sm + V_OFF + (vrow + vt * 16 + g) * 128;
                    const int u0 = ((2 * ks) ^ g) << 2;
                    const int u1 = ((2 * ks + 1) ^ g) << 2;
                    a[vt][0] = __float_as_uint(A[u0 + t4]);
                    a[vt][1] = __float_as_uint(A[1024 + u0 + t4]);  // row+8
                    a[vt][2] = __float_as_uint(A[u1 + t4]);
                    a[vt][3] = __float_as_uint(A[1024 + u1 + t4]);
                }
#pragma unroll
                for (int bn = 0; bn < 4; bn++) {
                    const float* B = P + (mcol + bn * 8 + g) * PST + k0 + t4;
                    b[bn][0] = __float_as_uint(B[0]);
                    b[bn][1] = __float_as_uint(B[4]);
                }
#pragma unroll
                for (int vt = 0; vt < 4; vt++)
#pragma unroll
                    for (int bn = 0; bn < 4; bn++)
                        mma8(o[vt][bn], a[vt], b[bn]);
            }

            bar_sync(2, 128);                 // all PV warps done reading V
            if (kt + 1 < NTILES) {
                const int n = kt + 1;
                issue_V(x + (size_t)(n >> 3) * 393216u + ((n & 7) << 7), t128);
            }
            cp_commit();
            bar_arrive(5 + (kt & 1), 256);    // P buffer empty
        }

        // ---- wait for rowsums, invert, normalize, store ----
        bar_sync(3, 256);                     // rowsums in RS4
        if (t128 < 64) {
            float s = sm[RS4_OFF + t128 * 2] + sm[RS4_OFF + t128 * 2 + 1];
            sm[RS_OFF + t128] = 1.0f / s;
        }
        bar_sync(2, 128);

        float* Og = out + (size_t)bq * 131072u + sq0;
#pragma unroll
        for (int bn = 0; bn < 4; bn++) {
            const int m0 = mcol + bn * 8 + 2 * t4;
            const float i0 = sm[RS_OFF + m0], i1 = sm[RS_OFF + m0 + 1];
#pragma unroll
            for (int vt = 0; vt < 4; vt++) {
                const int v = vrow + vt * 16 + g;
                *(float2*)(Og + (size_t)v * 1024 + m0) =
                    make_float2(o[vt][bn][0] * i0, o[vt][bn][1] * i1);
                *(float2*)(Og + (size_t)(v + 8) * 1024 + m0) =
                    make_float2(o[vt][bn][2] * i0, o[vt][bn][3] * i1);
            }
        }
    }
}

extern "C" void kernel_launch(void* const* d_in, const int* in_sizes, int n_in,
                              void* d_out, int out_size) {
    (void)in_sizes; (void)n_in; (void)out_size;
    const float* x = (const float*)d_in[0];
    float* out = (float*)d_out;
    cudaFuncSetAttribute(conv_attn_kernel,
                         cudaFuncAttributeMaxDynamicSharedMemorySize, SMEM_BYTES);
    conv_attn_kernel<<<128, 256, SMEM_BYTES>>>(x, out);
}

// round 5
// speedup vs baseline: 1.4297x; 1.4297x over previous
#include <cuda_runtime.h>
#include <cuda_fp16.h>
#include <cstdint>

// N=8192 tokens, D=128, x layout [8,384,32,32] fp32 (feature-major)
#define NTILES 64
#define SCALE 0.08838834764831845f  // 1/sqrt(128)

// smem layout (4-byte words)
#define Q_OFF   0          // Q half2: [m 64][j2 64] b32, swizzle j2 ^ ((m&7)<<2)
#define K_OFF   4096       // K fp32 staging: [j 128][c 128], unit swizzle
#define V_OFF   20480      // V fp32 staging: [v 128][c 128], unit swizzle
#define P_OFF   36864      // P half2: 2 bufs of [k2 64][m 64] b32
#define P_SZ    4096
#define RS4_OFF 45056      // 64 x 2 partial rowsums
#define RS_OFF  45184      // 64 inverse rowsums
#define SMEM_FLOATS 45248
#define SMEM_BYTES (SMEM_FLOATS * 4)   // 180992

extern __shared__ float sm[];

__device__ __forceinline__ uint32_t sptr(const void* p) {
    return (uint32_t)__cvta_generic_to_shared(p);
}
__device__ __forceinline__ void cp16(const float* smem_dst, const float* gsrc) {
    asm volatile("cp.async.cg.shared.global [%0], [%1], 16;"
                 :: "r"(sptr(smem_dst)), "l"(gsrc));
}
__device__ __forceinline__ void cp_commit() { asm volatile("cp.async.commit_group;"); }
__device__ __forceinline__ void cp_wait0()  { asm volatile("cp.async.wait_group 0;"); }

__device__ __forceinline__ void bar_sync(int id, int cnt) {
    asm volatile("bar.sync %0, %1;" :: "r"(id), "r"(cnt) : "memory");
}
__device__ __forceinline__ void bar_arrive(int id, int cnt) {
    asm volatile("bar.arrive %0, %1;" :: "r"(id), "r"(cnt) : "memory");
}

__device__ __forceinline__ uint32_t h2bits(float a, float b) {
    __half2 h = __floats2half2_rn(a, b);
    return *reinterpret_cast<uint32_t*>(&h);
}
__device__ __forceinline__ float h2sum(uint32_t u) {
    __half2 h = *reinterpret_cast<__half2*>(&u);
    float2 f = __half22float2(h);
    return f.x + f.y;
}
__device__ __forceinline__ void mma16(float c[4], const uint32_t a[4], const uint32_t b[2]) {
    asm volatile("mma.sync.aligned.m16n8k16.row.col.f32.f16.f16.f32 "
                 "{%0,%1,%2,%3}, {%4,%5,%6,%7}, {%8,%9}, {%0,%1,%2,%3};"
                 : "+f"(c[0]), "+f"(c[1]), "+f"(c[2]), "+f"(c[3])
                 : "r"(a[0]), "r"(a[1]), "r"(a[2]), "r"(a[3]),
                   "r"(b[0]), "r"(b[1]));
}

// K staging: row j, 16B-unit u stored at u ^ (((j>>1)&3)<<1)
// -> B-fragment reads (f32 col c ^ ((k2&3)<<3)) are conflict-free.
__device__ __forceinline__ void issue_K(const float* g, int t) {
#pragma unroll
    for (int i = 0; i < 32; i++) {
        int u = i * 128 + t;
        int r = u >> 5, c = u & 31;
        int sw = c ^ (((r >> 1) & 3) << 1);
        cp16(sm + K_OFF + r * 128 + (sw << 2), g + (size_t)r * 1024 + (c << 2));
    }
}
// V staging: row v, unit u stored at u ^ ((v&7)<<1)
// -> A-fragment float2 reads (pair p ^ ((v&7)<<2)) are conflict-free.
__device__ __forceinline__ void issue_V(const float* g, int t) {
#pragma unroll
    for (int i = 0; i < 32; i++) {
        int u = i * 128 + t;
        int r = u >> 5, c = u & 31;
        int sw = c ^ ((r & 7) << 1);
        cp16(sm + V_OFF + r * 128 + (sw << 2), g + (size_t)r * 1024 + (c << 2));
    }
}

__global__ void __launch_bounds__(256, 1)
conv_attn_kernel(const float* __restrict__ x, float* __restrict__ out) {
    const int tid  = threadIdx.x;
    const int lane = tid & 31;
    const int wid  = tid >> 5;
    const int g    = lane >> 2;
    const int t4   = lane & 3;

    const int bq  = blockIdx.x >> 4;
    const int sq0 = (blockIdx.x & 15) << 6;
    const float* Qg = x + (size_t)bq * 393216u + 262144u + sq0;

    uint32_t* smu = reinterpret_cast<uint32_t*>(sm);

    // ---- Q: load, pack feature-pairs to half2 [m][j2], swizzled ----
#pragma unroll
    for (int i = 0; i < 16; i++) {
        int idx = i * 256 + tid;
        int m = idx & 63, j2 = idx >> 6;
        float q0 = Qg[(size_t)(2 * j2) * 1024 + m];
        float q1 = Qg[(size_t)(2 * j2 + 1) * 1024 + m];
        smu[Q_OFF + m * 64 + (j2 ^ ((m & 7) << 2))] = h2bits(q0, q1);
    }

    // prefetch tile 0
    if (tid < 128) { issue_K(x + 131072u, tid); }
    else           { issue_V(x,           tid - 128); }
    cp_commit();
    __syncthreads();

    if (wid < 4) {
        // ============ S GROUP: S = Q K^T (fp16 mma), softmax, P(half2) ============
        const int qrow = (wid >> 1) * 32;
        const int scol = (wid & 1) * 64;
        float racc0[2] = {0.f, 0.f}, racc1[2] = {0.f, 0.f};

        for (int kt = 0; kt < NTILES; ++kt) {
            cp_wait0();
            bar_sync(1, 128);                 // K(kt) staged

            float c[2][8][4];
#pragma unroll
            for (int mt = 0; mt < 2; mt++)
#pragma unroll
                for (int nt = 0; nt < 8; nt++)
#pragma unroll
                    for (int r = 0; r < 4; r++) c[mt][nt][r] = 0.f;

#pragma unroll
            for (int ks = 0; ks < 8; ks++) {
                uint32_t a[2][4], b[8][2];
                const int j2a = (ks * 8 + t4) ^ (g << 2);
                const int j2b = (ks * 8 + t4 + 4) ^ (g << 2);
#pragma unroll
                for (int mt = 0; mt < 2; mt++) {
                    const int r0 = (qrow + mt * 16 + g) * 64;
                    a[mt][0] = smu[Q_OFF + r0 + j2a];
                    a[mt][1] = smu[Q_OFF + r0 + 512 + j2a];   // row+8
                    a[mt][2] = smu[Q_OFF + r0 + j2b];
                    a[mt][3] = smu[Q_OFF + r0 + 512 + j2b];
                }
                const int j0 = 16 * ks + 2 * t4;   // feature row, even
#pragma unroll
                for (int nt = 0; nt < 8; nt++) {
                    const int cs = (scol + nt * 8 + g) ^ (t4 << 3);
                    const float* K0 = sm + K_OFF + j0 * 128 + cs;
                    b[nt][0] = h2bits(K0[0],        K0[128]);        // j0, j0+1
                    b[nt][1] = h2bits(K0[8 * 128],  K0[9 * 128]);    // j0+8, j0+9
                }
#pragma unroll
                for (int mt = 0; mt < 2; mt++)
#pragma unroll
                    for (int nt = 0; nt < 8; nt++)
                        mma16(c[mt][nt], a[mt], b[nt]);
            }

            bar_sync(1, 128);                 // group done reading K
            if (kt + 1 < NTILES) {
                const int n = kt + 1;
                issue_K(x + (size_t)(n >> 3) * 393216u + 131072u + ((n & 7) << 7), tid);
            }
            cp_commit();

            if (kt >= 2) bar_sync(5 + (kt & 1), 256);   // P buffer free

            uint32_t* P = smu + P_OFF + (kt & 1) * P_SZ;
#pragma unroll
            for (int mt = 0; mt < 2; mt++) {
                float s0 = 0.f, s1 = 0.f;
                const int row = qrow + mt * 16 + g;
#pragma unroll
                for (int nt = 0; nt < 8; nt++) {
                    float e0 = __expf(c[mt][nt][0] * SCALE);
                    float e1 = __expf(c[mt][nt][1] * SCALE);
                    float e2 = __expf(c[mt][nt][2] * SCALE);
                    float e3 = __expf(c[mt][nt][3] * SCALE);
                    uint32_t u01 = h2bits(e0, e1);
                    uint32_t u23 = h2bits(e2, e3);
                    s0 += h2sum(u01); s1 += h2sum(u23);
                    const int k2 = (scol >> 1) + nt * 4 + t4;   // key pair index
                    P[k2 * 64 + (row ^ (t4 << 3))]       = u01;
                    P[k2 * 64 + ((row + 8) ^ (t4 << 3))] = u23;
                }
                s0 += __shfl_xor_sync(0xffffffffu, s0, 1);
                s0 += __shfl_xor_sync(0xffffffffu, s0, 2);
                s1 += __shfl_xor_sync(0xffffffffu, s1, 1);
                s1 += __shfl_xor_sync(0xffffffffu, s1, 2);
                racc0[mt] += s0; racc1[mt] += s1;
            }
            bar_arrive(3 + (kt & 1), 256);    // P(kt) full
        }

        if (t4 == 0) {
#pragma unroll
            for (int mt = 0; mt < 2; mt++) {
                const int row = qrow + mt * 16 + g;
                sm[RS4_OFF + row * 2 + (wid & 1)]       = racc0[mt];
                sm[RS4_OFF + (row + 8) * 2 + (wid & 1)] = racc1[mt];
            }
        }
        bar_arrive(3, 256);                   // rowsums ready
    } else {
        // ============ PV GROUP: O^T += V^T P^T (fp16 mma) ============
        const int widp = wid - 4;
        const int vrow = (widp >> 1) * 64;
        const int mcol = (widp & 1) * 32;
        const int t128 = tid - 128;

        float o[4][4][4];
#pragma unroll
        for (int a = 0; a < 4; a++)
#pragma unroll
            for (int b = 0; b < 4; b++)
#pragma unroll
                for (int r = 0; r < 4; r++) o[a][b][r] = 0.f;

        for (int kt = 0; kt < NTILES; ++kt) {
            bar_sync(3 + (kt & 1), 256);      // P(kt) ready
            cp_wait0();
            bar_sync(2, 128);                 // V(kt) staged

            const uint32_t* P = smu + P_OFF + (kt & 1) * P_SZ;
#pragma unroll
            for (int ks = 0; ks < 8; ks++) {
                uint32_t a[4][4], b[4][2];
                const int p0 = 2 * ((ks * 8 + t4) ^ (g << 2));      // swizzled f32 col
                const int p1 = 2 * ((ks * 8 + t4 + 4) ^ (g << 2));
#pragma unroll
                for (int vt = 0; vt < 4; vt++) {
                    const float* V0 = sm + V_OFF + (vrow + vt * 16 + g) * 128;
                    float2 f0 = *(const float2*)(V0 + p0);
                    float2 f1 = *(const float2*)(V0 + 8 * 128 + p0);  // row+8
                    float2 f2 = *(const float2*)(V0 + p1);
                    float2 f3 = *(const float2*)(V0 + 8 * 128 + p1);
                    a[vt][0] = h2bits(f0.x, f0.y);
                    a[vt][1] = h2bits(f1.x, f1.y);
                    a[vt][2] = h2bits(f2.x, f2.y);
                    a[vt][3] = h2bits(f3.x, f3.y);
                }
                const int k2a = ks * 8 + t4;
#pragma unroll
                for (int bn = 0; bn < 4; bn++) {
                    const int ms = (mcol + bn * 8 + g) ^ (t4 << 3);
                    b[bn][0] = P[k2a * 64 + ms];
                    b[bn][1] = P[(k2a + 4) * 64 + ms];
                }
#pragma unroll
                for (int vt = 0; vt < 4; vt++)
#pragma unroll
                    for (int bn = 0; bn < 4; bn++)
                        mma16(o[vt][bn], a[vt], b[bn]);
            }

            bar_sync(2, 128);                 // group done reading V
            if (kt + 1 < NTILES) {
                const int n = kt + 1;
                issue_V(x + (size_t)(n >> 3) * 393216u + ((n & 7) << 7), t128);
            }
            cp_commit();
            bar_arrive(5 + (kt & 1), 256);    // P buffer empty
        }

        // ---- rowsums -> inverse, normalize, store ----
        bar_sync(3, 256);
        if (t128 < 64) {
            float s = sm[RS4_OFF + t128 * 2] + sm[RS4_OFF + t128 * 2 + 1];
            sm[RS_OFF + t128] = 1.0f / s;
        }
        bar_sync(2, 128);

        float* Og = out + (size_t)bq * 131072u + sq0;
#pragma unroll
        for (int bn = 0; bn < 4; bn++) {
            const int m0 = mcol + bn * 8 + 2 * t4;
            const float i0 = sm[RS_OFF + m0], i1 = sm[RS_OFF + m0 + 1];
#pragma unroll
            for (int vt = 0; vt < 4; vt++) {
                const int v = vrow + vt * 16 + g;
                *(float2*)(Og + (size_t)v * 1024 + m0) =
                    make_float2(o[vt][bn][0] * i0, o[vt][bn][1] * i1);
                *(float2*)(Og + (size_t)(v + 8) * 1024 + m0) =
                    make_float2(o[vt][bn][2] * i0, o[vt][bn][3] * i1);
            }
        }
    }
}

extern "C" void kernel_launch(void* const* d_in, const int* in_sizes, int n_in,
                              void* d_out, int out_size) {
    (void)in_sizes; (void)n_in; (void)out_size;
    const float* x = (const float*)d_in[0];
    float* out = (float*)d_out;
    cudaFuncSetAttribute(conv_attn_kernel,
                         cudaFuncAttributeMaxDynamicSharedMemorySize, SMEM_BYTES);
    conv_attn_kernel<<<128, 256, SMEM_BYTES>>>(x, out);
}